// round 8
// baseline (speedup 1.0000x reference)
#include <cuda_runtime.h>
#include <cuda_bf16.h>

// GNNIntraAgg: out[b, :] = relu( (1/K) * sum_k features[neigh_ids[b,k], :] )
// B=16384, K=32, N=100000, D=256 (fp32).
//
// R8 = R4 (warp-per-row, smem-broadcast ids, LDG.256 evict_last, 4-deep
// batches, streaming stores) with __launch_bounds__(256,6): cap regs at 42
// so 6 CTAs/SM are resident (48 warps, 75% occ) while keeping 128 B in
// flight per thread. Shape sweep R2/R4/R7 shows the optimum is 128 B/thread
// with as many warps as that register budget allows.

#define K_NEIGH 32
#define WARPS_PER_BLOCK 8
#define THREADS (WARPS_PER_BLOCK * 32)   // 256
#define LBATCH 4                          // outstanding LDG.256 per thread

__device__ __forceinline__ void ldg256_evict_last(const float* p, float4& a, float4& b)
{
    asm volatile("ld.global.nc.L2::evict_last.v8.b32 "
                 "{%0,%1,%2,%3,%4,%5,%6,%7}, [%8];"
                 : "=f"(a.x), "=f"(a.y), "=f"(a.z), "=f"(a.w),
                   "=f"(b.x), "=f"(b.y), "=f"(b.z), "=f"(b.w)
                 : "l"(p));
}

__global__ __launch_bounds__(THREADS, 6)
void gnn_agg_kernel(const int* __restrict__ neigh_ids,
                    const float* __restrict__ feat,
                    float4* __restrict__ out,
                    int B)
{
    __shared__ int s_ids[WARPS_PER_BLOCK][K_NEIGH];

    const int tid  = threadIdx.x;
    const int row0 = blockIdx.x * WARPS_PER_BLOCK;

    // Stage this block's 8 rows of neighbor ids (256 ints, one per thread).
    {
        const int r = tid >> 5;
        const int k = tid & 31;
        s_ids[r][k] = neigh_ids[(row0 + r) * K_NEIGH + k];
    }
    __syncthreads();

    const int w    = tid >> 5;        // warp = output row within block
    const int lane = tid & 31;        // lane = 32B chunk of the feature row

    float acc[8];
#pragma unroll
    for (int i = 0; i < 8; ++i) acc[i] = 0.f;

#pragma unroll
    for (int kb = 0; kb < K_NEIGH; kb += LBATCH) {
        float4 va[LBATCH], vb[LBATCH];
        // Front-batch 4 independent 32B gathers -> 128 B in flight per thread.
#pragma unroll
        for (int j = 0; j < LBATCH; ++j) {
            const int id = s_ids[w][kb + j];             // warp-broadcast read
            const float* p = feat + (long)id * 256 + lane * 8;
            ldg256_evict_last(p, va[j], vb[j]);
        }
#pragma unroll
        for (int j = 0; j < LBATCH; ++j) {
            acc[0] += va[j].x;  acc[1] += va[j].y;
            acc[2] += va[j].z;  acc[3] += va[j].w;
            acc[4] += vb[j].x;  acc[5] += vb[j].y;
            acc[6] += vb[j].z;  acc[7] += vb[j].w;
        }
    }

    const float inv = 1.0f / (float)K_NEIGH;
    float4 o0, o1;
    o0.x = fmaxf(acc[0] * inv, 0.f);  o0.y = fmaxf(acc[1] * inv, 0.f);
    o0.z = fmaxf(acc[2] * inv, 0.f);  o0.w = fmaxf(acc[3] * inv, 0.f);
    o1.x = fmaxf(acc[4] * inv, 0.f);  o1.y = fmaxf(acc[5] * inv, 0.f);
    o1.z = fmaxf(acc[6] * inv, 0.f);  o1.w = fmaxf(acc[7] * inv, 0.f);

    // Streaming stores: don't evict the feature table from L2.
    float4* orow = out + (long)(row0 + w) * 64 + lane * 2;
    __stcs(orow,     o0);
    __stcs(orow + 1, o1);
}

extern "C" void kernel_launch(void* const* d_in, const int* in_sizes, int n_in,
                              void* d_out, int out_size)
{
    const int* neigh_ids = (const int*)d_in[0];     // [B, K] int32
    const float* feat    = (const float*)d_in[1];   // [N, D] fp32
    float4* out          = (float4*)d_out;          // [B, D] fp32

    const int B = in_sizes[0] / K_NEIGH;            // 16384
    const int grid = B / WARPS_PER_BLOCK;           // 2048

    gnn_agg_kernel<<<grid, THREADS>>>(neigh_ids, feat, out, B);
}

// round 9
// speedup vs baseline: 1.3831x; 1.3831x over previous
#include <cuda_runtime.h>
#include <cuda_bf16.h>

// GNNIntraAgg: out[b, :] = relu( (1/K) * sum_k features[neigh_ids[b,k], :] )
// B=16384, K=32, N=100000, D=256 (fp32).
//
// R9 = R4 (best: 36.8us) with the block barrier removed. Warp w's id row
// s_ids[w][*] is written only by warp w's own lanes, so __syncthreads()
// -> __syncwarp(): warps fully decoupled at CTA start, schedule untouched.
// No __launch_bounds__ — R7/R8 showed any register cap breaks the 4-deep
// LDG.256 batching ptxas finds naturally at 44 regs (5 CTAs/SM).

#define K_NEIGH 32
#define WARPS_PER_BLOCK 8
#define THREADS (WARPS_PER_BLOCK * 32)   // 256
#define LBATCH 4                          // outstanding LDG.256 per thread

__device__ __forceinline__ void ldg256_evict_last(const float* p, float4& a, float4& b)
{
    asm volatile("ld.global.nc.L2::evict_last.v8.b32 "
                 "{%0,%1,%2,%3,%4,%5,%6,%7}, [%8];"
                 : "=f"(a.x), "=f"(a.y), "=f"(a.z), "=f"(a.w),
                   "=f"(b.x), "=f"(b.y), "=f"(b.z), "=f"(b.w)
                 : "l"(p));
}

__global__ __launch_bounds__(THREADS)
void gnn_agg_kernel(const int* __restrict__ neigh_ids,
                    const float* __restrict__ feat,
                    float4* __restrict__ out,
                    int B)
{
    __shared__ int s_ids[WARPS_PER_BLOCK][K_NEIGH];

    const int tid  = threadIdx.x;
    const int row0 = blockIdx.x * WARPS_PER_BLOCK;

    const int w    = tid >> 5;        // warp = output row within block
    const int lane = tid & 31;        // lane = 32B chunk of the feature row

    // Warp-local id staging: warp w's lanes write s_ids[w][*] only.
    s_ids[w][lane] = neigh_ids[(row0 + w) * K_NEIGH + lane];
    __syncwarp();                     // intra-warp visibility; no block barrier

    float acc[8];
#pragma unroll
    for (int i = 0; i < 8; ++i) acc[i] = 0.f;

#pragma unroll
    for (int kb = 0; kb < K_NEIGH; kb += LBATCH) {
        float4 va[LBATCH], vb[LBATCH];
        // Front-batch 4 independent 32B gathers -> 128 B in flight per thread.
#pragma unroll
        for (int j = 0; j < LBATCH; ++j) {
            const int id = s_ids[w][kb + j];             // warp-broadcast read
            const float* p = feat + (long)id * 256 + lane * 8;
            ldg256_evict_last(p, va[j], vb[j]);
        }
#pragma unroll
        for (int j = 0; j < LBATCH; ++j) {
            acc[0] += va[j].x;  acc[1] += va[j].y;
            acc[2] += va[j].z;  acc[3] += va[j].w;
            acc[4] += vb[j].x;  acc[5] += vb[j].y;
            acc[6] += vb[j].z;  acc[7] += vb[j].w;
        }
    }

    const float inv = 1.0f / (float)K_NEIGH;
    float4 o0, o1;
    o0.x = fmaxf(acc[0] * inv, 0.f);  o0.y = fmaxf(acc[1] * inv, 0.f);
    o0.z = fmaxf(acc[2] * inv, 0.f);  o0.w = fmaxf(acc[3] * inv, 0.f);
    o1.x = fmaxf(acc[4] * inv, 0.f);  o1.y = fmaxf(acc[5] * inv, 0.f);
    o1.z = fmaxf(acc[6] * inv, 0.f);  o1.w = fmaxf(acc[7] * inv, 0.f);

    // Streaming stores: don't evict the feature table from L2.
    float4* orow = out + (long)(row0 + w) * 64 + lane * 2;
    __stcs(orow,     o0);
    __stcs(orow + 1, o1);
}

extern "C" void kernel_launch(void* const* d_in, const int* in_sizes, int n_in,
                              void* d_out, int out_size)
{
    const int* neigh_ids = (const int*)d_in[0];     // [B, K] int32
    const float* feat    = (const float*)d_in[1];   // [N, D] fp32
    float4* out          = (float4*)d_out;          // [B, D] fp32

    const int B = in_sizes[0] / K_NEIGH;            // 16384
    const int grid = B / WARPS_PER_BLOCK;           // 2048

    gnn_agg_kernel<<<grid, THREADS>>>(neigh_ids, feat, out, B);
}

// round 10
// speedup vs baseline: 1.3944x; 1.0082x over previous
#include <cuda_runtime.h>
#include <cuda_bf16.h>

// GNNIntraAgg: out[b, :] = relu( (1/K) * sum_k features[neigh_ids[b,k], :] )
// B=16384, K=32, N=100000, D=256 (fp32).
//
// R10 = R9 (best: 35.6us) with 4-warp CTAs (128 threads, grid 4096):
// 44 regs x 128 thr = 5632 regs/CTA -> 11 CTAs/SM = 44 resident warps
// (68.8% vs 62.5%), finer scheduling granularity, identical per-warp code.
// We are at the LTS (L2->SM) bandwidth ceiling: 536 MB compulsory gather
// traffic at ~15 TB/s effective; all remaining knobs sweep worse.

#define K_NEIGH 32
#define WARPS_PER_BLOCK 4
#define THREADS (WARPS_PER_BLOCK * 32)   // 128
#define LBATCH 4                          // outstanding LDG.256 per thread

__device__ __forceinline__ void ldg256_evict_last(const float* p, float4& a, float4& b)
{
    asm volatile("ld.global.nc.L2::evict_last.v8.b32 "
                 "{%0,%1,%2,%3,%4,%5,%6,%7}, [%8];"
                 : "=f"(a.x), "=f"(a.y), "=f"(a.z), "=f"(a.w),
                   "=f"(b.x), "=f"(b.y), "=f"(b.z), "=f"(b.w)
                 : "l"(p));
}

__global__ __launch_bounds__(THREADS)
void gnn_agg_kernel(const int* __restrict__ neigh_ids,
                    const float* __restrict__ feat,
                    float4* __restrict__ out,
                    int B)
{
    __shared__ int s_ids[WARPS_PER_BLOCK][K_NEIGH];

    const int tid  = threadIdx.x;
    const int row0 = blockIdx.x * WARPS_PER_BLOCK;

    const int w    = tid >> 5;        // warp = output row within block
    const int lane = tid & 31;        // lane = 32B chunk of the feature row

    // Warp-local id staging: warp w's lanes write s_ids[w][*] only.
    s_ids[w][lane] = neigh_ids[(row0 + w) * K_NEIGH + lane];
    __syncwarp();                     // intra-warp visibility; no block barrier

    float acc[8];
#pragma unroll
    for (int i = 0; i < 8; ++i) acc[i] = 0.f;

#pragma unroll
    for (int kb = 0; kb < K_NEIGH; kb += LBATCH) {
        float4 va[LBATCH], vb[LBATCH];
        // Front-batch 4 independent 32B gathers -> 128 B in flight per thread.
#pragma unroll
        for (int j = 0; j < LBATCH; ++j) {
            const int id = s_ids[w][kb + j];             // warp-broadcast read
            const float* p = feat + (long)id * 256 + lane * 8;
            ldg256_evict_last(p, va[j], vb[j]);
        }
#pragma unroll
        for (int j = 0; j < LBATCH; ++j) {
            acc[0] += va[j].x;  acc[1] += va[j].y;
            acc[2] += va[j].z;  acc[3] += va[j].w;
            acc[4] += vb[j].x;  acc[5] += vb[j].y;
            acc[6] += vb[j].z;  acc[7] += vb[j].w;
        }
    }

    const float inv = 1.0f / (float)K_NEIGH;
    float4 o0, o1;
    o0.x = fmaxf(acc[0] * inv, 0.f);  o0.y = fmaxf(acc[1] * inv, 0.f);
    o0.z = fmaxf(acc[2] * inv, 0.f);  o0.w = fmaxf(acc[3] * inv, 0.f);
    o1.x = fmaxf(acc[4] * inv, 0.f);  o1.y = fmaxf(acc[5] * inv, 0.f);
    o1.z = fmaxf(acc[6] * inv, 0.f);  o1.w = fmaxf(acc[7] * inv, 0.f);

    // Streaming stores: don't evict the feature table from L2.
    float4* orow = out + (long)(row0 + w) * 64 + lane * 2;
    __stcs(orow,     o0);
    __stcs(orow + 1, o1);
}

extern "C" void kernel_launch(void* const* d_in, const int* in_sizes, int n_in,
                              void* d_out, int out_size)
{
    const int* neigh_ids = (const int*)d_in[0];     // [B, K] int32
    const float* feat    = (const float*)d_in[1];   // [N, D] fp32
    float4* out          = (float4*)d_out;          // [B, D] fp32

    const int B = in_sizes[0] / K_NEIGH;            // 16384
    const int grid = B / WARPS_PER_BLOCK;           // 4096

    gnn_agg_kernel<<<grid, THREADS>>>(neigh_ids, feat, out, B);
}